// round 10
// baseline (speedup 1.0000x reference)
#include <cuda_runtime.h>
#include <cstdint>

#define BATCH   16384
#define NCLS    1024
#define FEAT    512
#define F4      (FEAT / 4)      // 128 float4 per feature row
#define ALPHA   0.5f

#define NBLK    128             // one balanced wave
#define THREADS 512             // 16 warps: class k owned by warp pair {2k, 2k+1}
#define CPB     8               // classes per block
#define NWARP   16
#define MAXS    64              // rows per class: Poisson(16)

#define DEPTH   5               // TMA ring depth (rows in flight per warp)
#define ROWB    2048            // bytes per feature row
#define RING_BYTES (NWARP * DEPTH * ROWB)   // 160 KB dynamic smem

// ---- mbarrier / TMA-bulk helpers -----------------------------------------
__device__ __forceinline__ void mbar_init(uint32_t a, uint32_t cnt) {
    asm volatile("mbarrier.init.shared.b64 [%0], %1;" :: "r"(a), "r"(cnt) : "memory");
}
__device__ __forceinline__ void mbar_expect_tx(uint32_t a, uint32_t bytes) {
    asm volatile("mbarrier.arrive.expect_tx.shared.b64 _, [%0], %1;"
                 :: "r"(a), "r"(bytes) : "memory");
}
__device__ __forceinline__ void tma_bulk_row(uint32_t dst, const void* src,
                                             uint32_t mbar, float dep) {
    // 'dep' input forces all consuming FFMAs of the previous slot contents to
    // be ready before this issues (ordering belt-and-braces; see call sites).
    asm volatile(
        "cp.async.bulk.shared::cluster.global.mbarrier::complete_tx::bytes "
        "[%0], [%1], %2, [%3];"
        :: "r"(dst), "l"(src), "r"((uint32_t)ROWB), "r"(mbar), "f"(dep)
        : "memory");
}
__device__ __forceinline__ void mbar_wait(uint32_t a, uint32_t ph) {
    uint32_t done;
    asm volatile(
        "{\n\t.reg .pred p;\n\t"
        "mbarrier.try_wait.parity.acquire.cta.shared::cta.b64 p, [%1], %2;\n\t"
        "selp.b32 %0, 1, 0, p;\n\t}"
        : "=r"(done) : "r"(a), "r"(ph) : "memory");
    if (!done) {
        asm volatile(
            "{\n\t.reg .pred P1;\n\t"
            "W_%=:\n\t"
            "mbarrier.try_wait.parity.acquire.cta.shared::cta.b64 P1, [%0], %1, 0x989680;\n\t"
            "@P1 bra.uni D_%=;\n\t"
            "bra.uni W_%=;\n\t"
            "D_%=:\n\t}"
            :: "r"(a), "r"(ph) : "memory");
    }
}

// Phase 1: per-block label scan (R4-proven; blocks pipeline independently,
//          no grid barrier).
// Phase 2: warp pair {2k,2k+1} per class, rows even/odd. Each warp streams
//          its rows through a 5-deep TMA-bulk smem ring (one UBLKCP per 2KB
//          row, issued by lane 0; no LSU-queue occupancy; 10KB in flight per
//          warp). Consume via conflict-free LDS.128; ||f-ctr||^2 via shfl ->
//          out[b]; class sum in regs; pair merged via smem; center written.
__global__ void __launch_bounds__(THREADS, 1)
k_all(const float4* __restrict__ features,
      const float4* __restrict__ centers,
      const int4*   __restrict__ labels4,
      float* __restrict__ out) {
    __shared__ int      s_cnt[CPB];
    __shared__ int      s_list[CPB][MAXS];
    __shared__ float4   s_part[CPB][F4];        // 16KB pair partials
    __shared__ uint64_t s_mbar[NWARP][DEPTH];   // per-warp per-slot barriers
    extern __shared__ char ring[];              // 160KB staging rings

    const int tid = threadIdx.x;
    const int w   = tid >> 5;
    const int l   = tid & 31;
    const int c0  = blockIdx.x * CPB;

    if (tid < CPB) s_cnt[tid] = 0;
    if (l == 0) {
        const uint32_t mb = (uint32_t)__cvta_generic_to_shared(&s_mbar[w][0]);
        #pragma unroll
        for (int s = 0; s < DEPTH; s++) mbar_init(mb + 8u * s, 1);
        asm volatile("fence.proxy.async.shared::cta;" ::: "memory");
    }
    __syncthreads();

    // ---- Phase 1: scan all labels, collect rows of classes c0..c0+7
    #pragma unroll
    for (int it = 0; it < (BATCH / 4) / THREADS; ++it) {   // 8 iterations
        const int idx = it * THREADS + tid;
        const int4 v  = labels4[idx];
        const int  b  = idx * 4;
        int d;
        d = v.x - c0; if ((unsigned)d < CPB) { int s = atomicAdd(&s_cnt[d], 1); if (s < MAXS) s_list[d][s] = b;     }
        d = v.y - c0; if ((unsigned)d < CPB) { int s = atomicAdd(&s_cnt[d], 1); if (s < MAXS) s_list[d][s] = b + 1; }
        d = v.z - c0; if ((unsigned)d < CPB) { int s = atomicAdd(&s_cnt[d], 1); if (s < MAXS) s_list[d][s] = b + 2; }
        d = v.w - c0; if ((unsigned)d < CPB) { int s = atomicAdd(&s_cnt[d], 1); if (s < MAXS) s_list[d][s] = b + 3; }
    }
    __syncthreads();

    // ---- Phase 2
    const int k   = w >> 1;                // class 0..7 within block
    const int h   = w & 1;                 // half: even/odd rows
    const int c   = c0 + k;
    const int cnt = min(s_cnt[k], MAXS);
    const int nloc = (cnt > h) ? ((cnt - h + 1) >> 1) : 0;   // my rows (<=32)

    const uint32_t mb0 = (uint32_t)__cvta_generic_to_shared(&s_mbar[w][0]);
    char* myring = ring + w * (DEPTH * ROWB);
    const uint32_t ring0 = (uint32_t)__cvta_generic_to_shared(myring);

    float4 ctr[4];
    #pragma unroll
    for (int j = 0; j < 4; j++)
        ctr[j] = centers[c * F4 + l + 32 * j];

    float4 acc[4];
    #pragma unroll
    for (int j = 0; j < 4; j++)
        acc[j] = make_float4(0.f, 0.f, 0.f, 0.f);

    // Prologue: lane 0 fills the ring
    if (l == 0) {
        #pragma unroll
        for (int n = 0; n < DEPTH; n++) {
            if (n < nloc) {
                const int b = s_list[k][h + 2 * n];
                mbar_expect_tx(mb0 + 8u * n, ROWB);
                tma_bulk_row(ring0 + (uint32_t)(n * ROWB), features + b * F4,
                             mb0 + 8u * n, 0.f);
            }
        }
    }
    __syncwarp();

    int slot = 0, phase = 0;
    for (int n = 0; n < nloc; n++) {
        mbar_wait(mb0 + 8u * slot, (uint32_t)phase);
        const float4* sp = (const float4*)(myring + slot * ROWB);
        float sq = 0.f;
        #pragma unroll
        for (int j = 0; j < 4; j++) {
            const float4 f = sp[j * 32 + l];
            acc[j].x += f.x; acc[j].y += f.y; acc[j].z += f.z; acc[j].w += f.w;
            const float dx = f.x - ctr[j].x;
            const float dy = f.y - ctr[j].y;
            const float dz = f.z - ctr[j].z;
            const float dw = f.w - ctr[j].w;
            sq += dx * dx + dy * dy + dz * dz + dw * dw;
        }
        #pragma unroll
        for (int o = 16; o; o >>= 1)
            sq += __shfl_xor_sync(0xffffffffu, sq, o);
        if (l == 0) {
            out[s_list[k][h + 2 * n]] = sq;
            // refill this slot with row n+DEPTH; sq dependency guarantees the
            // LDS reads of this slot completed before the TMA overwrite.
            const int m = n + DEPTH;
            if (m < nloc) {
                const int b2 = s_list[k][h + 2 * m];
                mbar_expect_tx(mb0 + 8u * slot, ROWB);
                tma_bulk_row(ring0 + (uint32_t)(slot * ROWB),
                             features + b2 * F4, mb0 + 8u * slot, sq);
            }
        }
        if (++slot == DEPTH) { slot = 0; phase ^= 1; }
    }

    // ---- merge the warp pair
    if (h == 1) {
        #pragma unroll
        for (int j = 0; j < 4; j++)
            s_part[k][l + 32 * j] = acc[j];
    }
    __syncthreads();

    if (h == 0) {
        const float fc = (float)cnt;
        const float sc = ALPHA / (fc + 1.0f);
        float4* __restrict__ cout = reinterpret_cast<float4*>(out + BATCH);
        #pragma unroll
        for (int j = 0; j < 4; j++) {
            const float4 p = s_part[k][l + 32 * j];
            const float4 m = ctr[j];
            const float tx = acc[j].x + p.x;
            const float ty = acc[j].y + p.y;
            const float tz = acc[j].z + p.z;
            const float tw = acc[j].w + p.w;
            float4 nc;
            // delta = cnt*ctr - sum_features ; new = ctr - alpha*delta/(cnt+1)
            nc.x = m.x - sc * (fc * m.x - tx);
            nc.y = m.y - sc * (fc * m.y - ty);
            nc.z = m.z - sc * (fc * m.z - tz);
            nc.w = m.w - sc * (fc * m.w - tw);
            cout[c * F4 + l + 32 * j] = nc;
        }
    }
}

extern "C" void kernel_launch(void* const* d_in, const int* in_sizes, int n_in,
                              void* d_out, int out_size) {
    const float4* features = (const float4*)d_in[0];   // [16384, 512] f32
    const float4* centers  = (const float4*)d_in[1];   // [1024, 512] f32
    const int4*   labels4  = (const int4*)d_in[2];     // [16384] i32
    float*        out      = (float*)d_out;            // [16384 + 1024*512] f32

    static bool attr_set = false;
    if (!attr_set) {
        cudaFuncSetAttribute(k_all, cudaFuncAttributeMaxDynamicSharedMemorySize,
                             RING_BYTES);
        attr_set = true;
    }
    k_all<<<NBLK, THREADS, RING_BYTES>>>(features, centers, labels4, out);
}

// round 11
// speedup vs baseline: 1.3463x; 1.3463x over previous
#include <cuda_runtime.h>
#include <cstdint>

#define BATCH   16384
#define NCLS    1024
#define FEAT    512
#define F4      (FEAT / 4)     // 128 float4 per feature row
#define ALPHA   0.5f

#define CPB     8              // classes per block
#define NBLK    (NCLS / CPB)   // 128 blocks -> one balanced wave
#define THREADS 512            // 16 warps: class k owned by warp pair {2k, 2k+1}
#define NWARP   16
#define MAXS    64             // rows per class: Poisson(16); cap
#define MAXH    32             // rows per half-warp (MAXS/2)

// deferred-reduction scratch: [warp][row][lane] with +1 padding lane
#define SQ_BYTES (NWARP * MAXH * 33 * 4)    // 67.5 KB dynamic smem

// Phase 1: per-block label scan (blocks pipeline independently; no barrier).
// Phase 2: warp pair {2k,2k+1} per class (rows even/odd), 2-row unroll =
//          8 independent LDG.E.128 per warp-iter. HOT LOOP HAS NO REDUCTION:
//          per-lane sq partials go to padded smem; a single deferred pass
//          (lane i reduces row i, conflict-free stride-33 LDS) produces
//          out[b]. Class feature sum in regs; pair merge via smem; center
//          written directly.
__global__ void __launch_bounds__(THREADS, 1)
k_all(const float4* __restrict__ features,
      const float4* __restrict__ centers,
      const int4*   __restrict__ labels4,
      float* __restrict__ out) {
    __shared__ int    s_cnt[CPB];
    __shared__ int    s_list[CPB][MAXS];
    __shared__ float4 s_part[CPB][F4];       // 16KB pair partials
    extern __shared__ float s_sq[];          // [NWARP][MAXH][33]

    const int tid = threadIdx.x;
    const int c0  = blockIdx.x * CPB;

    if (tid < CPB) s_cnt[tid] = 0;
    __syncthreads();

    // ---- Phase 1: scan all labels, collect rows of classes c0..c0+7
    #pragma unroll
    for (int it = 0; it < (BATCH / 4) / THREADS; ++it) {   // 8 iterations
        const int idx = it * THREADS + tid;
        const int4 v  = labels4[idx];
        const int  b  = idx * 4;
        int d;
        d = v.x - c0; if ((unsigned)d < CPB) { int s = atomicAdd(&s_cnt[d], 1); if (s < MAXS) s_list[d][s] = b;     }
        d = v.y - c0; if ((unsigned)d < CPB) { int s = atomicAdd(&s_cnt[d], 1); if (s < MAXS) s_list[d][s] = b + 1; }
        d = v.z - c0; if ((unsigned)d < CPB) { int s = atomicAdd(&s_cnt[d], 1); if (s < MAXS) s_list[d][s] = b + 2; }
        d = v.w - c0; if ((unsigned)d < CPB) { int s = atomicAdd(&s_cnt[d], 1); if (s < MAXS) s_list[d][s] = b + 3; }
    }
    __syncthreads();

    // ---- Phase 2
    const int w = tid >> 5;
    const int l = tid & 31;
    const int k = w >> 1;                    // class 0..7 within block
    const int h = w & 1;                     // half: even/odd rows
    const int c = c0 + k;
    const int cnt  = min(s_cnt[k], MAXS);
    const int nloc = (cnt > h) ? ((cnt - h + 1) >> 1) : 0;   // my rows (<=32)

    float* __restrict__ mysq = s_sq + w * (MAXH * 33);

    float4 ctr[4];
    #pragma unroll
    for (int j = 0; j < 4; j++)
        ctr[j] = centers[c * F4 + l + 32 * j];

    float4 acc[4];
    #pragma unroll
    for (int j = 0; j < 4; j++)
        acc[j] = make_float4(0.f, 0.f, 0.f, 0.f);

    // ---- hot loop: loads + FFMA + STS only (no shfl, no divergent store)
    int i = 0;
    for (; i + 1 < nloc; i += 2) {
        const int b0 = s_list[k][h + 2 * i];
        const int b1 = s_list[k][h + 2 * (i + 1)];
        float4 f0[4], f1[4];
        #pragma unroll
        for (int j = 0; j < 4; j++) {
            f0[j] = features[b0 * F4 + l + 32 * j];
            f1[j] = features[b1 * F4 + l + 32 * j];
        }
        float sq0 = 0.f, sq1 = 0.f;
        #pragma unroll
        for (int j = 0; j < 4; j++) {
            acc[j].x += f0[j].x + f1[j].x;
            acc[j].y += f0[j].y + f1[j].y;
            acc[j].z += f0[j].z + f1[j].z;
            acc[j].w += f0[j].w + f1[j].w;
            float dx, dy, dz, dw;
            dx = f0[j].x - ctr[j].x; dy = f0[j].y - ctr[j].y;
            dz = f0[j].z - ctr[j].z; dw = f0[j].w - ctr[j].w;
            sq0 += dx * dx + dy * dy + dz * dz + dw * dw;
            dx = f1[j].x - ctr[j].x; dy = f1[j].y - ctr[j].y;
            dz = f1[j].z - ctr[j].z; dw = f1[j].w - ctr[j].w;
            sq1 += dx * dx + dy * dy + dz * dz + dw * dw;
        }
        mysq[i * 33 + l]       = sq0;
        mysq[(i + 1) * 33 + l] = sq1;
    }
    if (i < nloc) {
        const int b = s_list[k][h + 2 * i];
        float sq = 0.f;
        #pragma unroll
        for (int j = 0; j < 4; j++) {
            const float4 f = features[b * F4 + l + 32 * j];
            acc[j].x += f.x; acc[j].y += f.y; acc[j].z += f.z; acc[j].w += f.w;
            const float dx = f.x - ctr[j].x;
            const float dy = f.y - ctr[j].y;
            const float dz = f.z - ctr[j].z;
            const float dw = f.w - ctr[j].w;
            sq += dx * dx + dy * dy + dz * dz + dw * dw;
        }
        mysq[i * 33 + l] = sq;
    }
    __syncwarp();

    // ---- deferred per-row reduction: lane i owns row i
    if (l < nloc) {
        const int b = s_list[k][h + 2 * l];
        const float* row = mysq + l * 33;
        float s = 0.f;
        #pragma unroll
        for (int j = 0; j < 32; j++) s += row[j];
        out[b] = s;
    }

    // ---- merge the warp pair
    if (h == 1) {
        #pragma unroll
        for (int j = 0; j < 4; j++)
            s_part[k][l + 32 * j] = acc[j];
    }
    __syncthreads();

    if (h == 0) {
        const float fc = (float)cnt;
        const float sc = ALPHA / (fc + 1.0f);
        float4* __restrict__ cout = reinterpret_cast<float4*>(out + BATCH);
        #pragma unroll
        for (int j = 0; j < 4; j++) {
            const float4 p = s_part[k][l + 32 * j];
            const float4 m = ctr[j];
            const float tx = acc[j].x + p.x;
            const float ty = acc[j].y + p.y;
            const float tz = acc[j].z + p.z;
            const float tw = acc[j].w + p.w;
            float4 nc;
            // delta = cnt*ctr - sum_features ; new = ctr - alpha*delta/(cnt+1)
            nc.x = m.x - sc * (fc * m.x - tx);
            nc.y = m.y - sc * (fc * m.y - ty);
            nc.z = m.z - sc * (fc * m.z - tz);
            nc.w = m.w - sc * (fc * m.w - tw);
            cout[c * F4 + l + 32 * j] = nc;
        }
    }
}

extern "C" void kernel_launch(void* const* d_in, const int* in_sizes, int n_in,
                              void* d_out, int out_size) {
    const float4* features = (const float4*)d_in[0];   // [16384, 512] f32
    const float4* centers  = (const float4*)d_in[1];   // [1024, 512] f32
    const int4*   labels4  = (const int4*)d_in[2];     // [16384] i32
    float*        out      = (float*)d_out;            // [16384 + 1024*512] f32

    static bool attr_set = false;
    if (!attr_set) {
        cudaFuncSetAttribute(k_all, cudaFuncAttributeMaxDynamicSharedMemorySize,
                             SQ_BYTES);
        attr_set = true;
    }
    k_all<<<NBLK, THREADS, SQ_BYTES>>>(features, centers, labels4, out);
}